// round 16
// baseline (speedup 1.0000x reference)
#include <cuda_runtime.h>
#include <cstdint>

// self_attention_76416058130984 — GB300 sm_103a
// frames: [4, B=8, C=64, H=160, W=160] fp32 -> out: [8, 256, 160, 160] fp32
//
// Per pixel: E_ij(c) = exp(x_i[c]*x_j[c]) (symmetric, 10 unique per channel),
// denom_i = sum_{j,c} E_ij(c),  out_i[c] = (sum_j E_ij(c)*x_j[c]) / denom_i.
// No max-subtraction needed (logits bounded ~40, fp32 safe; softmax shift-invariant).
//
// R16 = R11's exact structure (cp.async double-buffer, lane=pixel mapping,
// pd cross-warp reduce, y in smem, plain stores, TPB=4, 4 barriers/tile)
// at HALF tile size: WTILE=16, SPAD=20 -> ~45KB smem -> 4-5 blocks/SM
// instead of 3, and ~2.5us tile quanta instead of 5us. Attacks the measured
// limiter: resident-block phase alignment starving DRAM. R12/R13/R15 lessons
// kept: no .cs hints, y not in registers, TPB=4.

#define B_       8
#define C_       64
#define H_       160
#define W_       160
#define HW_      (H_*W_)            // 25600
#define WTILE    16
#define NTHREADS 256
#define TPB      4                  // tiles per block
#define NTILES   (B_*H_*(W_/WTILE)) // 12800
#define SPAD     20                 // row stride: 16 px + 4 pad (16B-aligned, conflict-free)
#define TILE_F   (4*C_*SPAD)        // 5120 floats = 20KB
#define PD_OFF   (2*TILE_F)         // pd[16 slices][4 i][16 px] = 1024 floats
#define INVD_OFF (PD_OFF + 16*4*16) // invd[4 i][16 px] = 64 floats
#define SMEM_F   (INVD_OFF + 4*16)  // 11328 floats
#define SMEM_BYTES (SMEM_F*4)       // 45312 B

__device__ __forceinline__ float ex2a(float x) {
    float y; asm("ex2.approx.f32 %0, %1;" : "=f"(y) : "f"(x)); return y;
}
__device__ __forceinline__ float rcpa(float x) {
    float y; asm("rcp.approx.f32 %0, %1;" : "=f"(y) : "f"(x)); return y;
}
__device__ __forceinline__ void cpasync16(uint32_t dst_s, const void* src_g) {
    asm volatile("cp.async.cg.shared.global [%0], [%1], 16;"
                 :: "r"(dst_s), "l"(src_g));
}

// 10 unique exps -> row sums r[i] and gated sums y[i]
__device__ __forceinline__ void attn4(const float a[4], float y[4], float r[4]) {
    const float L2E = 1.44269504f;   // log2(e)
    float b0 = a[0]*L2E, b1 = a[1]*L2E, b2 = a[2]*L2E, b3 = a[3]*L2E;
    float e00 = ex2a(a[0]*b0), e01 = ex2a(a[0]*b1), e02 = ex2a(a[0]*b2), e03 = ex2a(a[0]*b3);
    float e11 = ex2a(a[1]*b1), e12 = ex2a(a[1]*b2), e13 = ex2a(a[1]*b3);
    float e22 = ex2a(a[2]*b2), e23 = ex2a(a[2]*b3);
    float e33 = ex2a(a[3]*b3);
    r[0] = (e00+e01)+(e02+e03);
    r[1] = (e01+e11)+(e12+e13);
    r[2] = (e02+e12)+(e22+e23);
    r[3] = (e03+e13)+(e23+e33);
    y[0] = fmaf(e00,a[0], fmaf(e01,a[1], fmaf(e02,a[2], e03*a[3])));
    y[1] = fmaf(e01,a[0], fmaf(e11,a[1], fmaf(e12,a[2], e13*a[3])));
    y[2] = fmaf(e02,a[0], fmaf(e12,a[1], fmaf(e22,a[2], e23*a[3])));
    y[3] = fmaf(e03,a[0], fmaf(e13,a[1], fmaf(e23,a[2], e33*a[3])));
}

// async-copy one 16-pixel tile (256 rows x 16 floats, SPAD-strided) into smem
__device__ __forceinline__ void ca_tile(uint32_t dst_s, int tid, int t,
                                        const float* __restrict__ frames) {
    const int tl = tid % (W_/WTILE);
    const int h  = (tid / (W_/WTILE)) % H_;
    const int b  = tid / ((W_/WTILE)*H_);
    const int sp = h*W_ + tl*WTILE;
    #pragma unroll
    for (int m = 0; m < 4; ++m) {
        const int f   = m*NTHREADS + t;   // 0..1023 quad index
        const int row = f >> 2;           // j*64 + c
        const int q   = f & 3;
        const int j   = row >> 6;
        const int c   = row & 63;
        cpasync16(dst_s + (uint32_t)(row*SPAD + q*4)*4u,
                  frames + ((j*B_ + b)*C_ + c)*HW_ + sp + q*4);
    }
}

__global__ void __launch_bounds__(NTHREADS)
self_attn_fused_kernel(const float* __restrict__ frames, float* __restrict__ out)
{
    extern __shared__ float s[];
    const uint32_t s_u32 = (uint32_t)__cvta_generic_to_shared(s);
    const int t    = threadIdx.x;
    const int warp = t >> 5, lane = t & 31;
    const int sub  = lane >> 4;          // half-warp: channel sub-slice
    const int px   = lane & 15;          // pixel 0..15
    const int cbase = warp*8 + sub*4;    // this thread's 4 channels
    const int slice = warp*2 + sub;      // pd slice 0..15
    const int first = blockIdx.x * TPB;

    // prologue: prefetch tile 0
    ca_tile(s_u32, first, t, frames);
    asm volatile("cp.async.commit_group;");

    for (int k = 0; k < TPB; ++k) {
        float* buf = s + (k & 1)*TILE_F;

        // prefetch tile k+1 into the other buffer, then wait for tile k
        if (k + 1 < TPB) {
            ca_tile(s_u32 + (uint32_t)(((k+1)&1)*TILE_F)*4u, first+k+1, t, frames);
            asm volatile("cp.async.commit_group;");
            asm volatile("cp.async.wait_group 1;");
        } else {
            asm volatile("cp.async.wait_group 0;");
        }
        __syncthreads();

        // ---- Phase 2a: thread (slice, px) owns 4 channels x 1 pixel.
        // Reads a[4], accumulates partial denominators, overwrites the same
        // words with unnormalized y (per-thread in-place, disjoint words).
        // Banks: stride SPAD=20 -> sub0/sub1 rows differ by 4 (80B = half
        // crossbar) -> conflict-free.
        float d[4] = {0.f, 0.f, 0.f, 0.f};
        #pragma unroll
        for (int cc = 0; cc < 4; ++cc) {
            const int c = cbase + cc;
            float a[4];
            #pragma unroll
            for (int j = 0; j < 4; ++j)
                a[j] = buf[(j*C_ + c)*SPAD + px];
            float y[4], r[4];
            attn4(a, y, r);
            #pragma unroll
            for (int i = 0; i < 4; ++i) {
                d[i] += r[i];
                buf[(i*C_ + c)*SPAD + px] = y[i];
            }
        }
        #pragma unroll
        for (int i = 0; i < 4; ++i)
            s[PD_OFF + (slice*4 + i)*16 + px] = d[i];
        __syncthreads();

        // ---- Phase 2b: reduce partial denoms across 16 slices, one rcp each
        if (t < 64) {
            const int i = t >> 4, p = t & 15;
            float sum = 0.f;
            #pragma unroll
            for (int w = 0; w < 16; ++w)
                sum += s[PD_OFF + (w*4 + i)*16 + p];
            s[INVD_OFF + i*16 + p] = rcpa(sum);
        }
        __syncthreads();

        // ---- Phase 3: normalize + coalesced store (64B rows, sector-aligned)
        {
            const int tid = first + k;
            const int tl = tid % (W_/WTILE);
            const int h  = (tid / (W_/WTILE)) % H_;
            const int b  = tid / ((W_/WTILE)*H_);
            const int sp = h*W_ + tl*WTILE;
            #pragma unroll
            for (int m = 0; m < 4; ++m) {
                const int f   = m*NTHREADS + t;
                const int row = f >> 2;       // i*64 + c
                const int q4  = (f & 3)*4;
                const int i   = row >> 6;
                const float4 iv = *reinterpret_cast<const float4*>(
                    s + INVD_OFF + i*16 + q4);
                const float* yp = buf + row*SPAD + q4;
                float4 v = make_float4(yp[0]*iv.x, yp[1]*iv.y,
                                       yp[2]*iv.z, yp[3]*iv.w);
                *reinterpret_cast<float4*>(
                    out + (b*4*C_ + row)*HW_ + sp + q4) = v;
            }
        }
        // guard buf reuse vs next iteration's prefetch; elide on last tile
        if (k + 1 < TPB) __syncthreads();
    }
}

extern "C" void kernel_launch(void* const* d_in, const int* in_sizes, int n_in,
                              void* d_out, int out_size)
{
    const float* frames = (const float*)d_in[0];
    float* out = (float*)d_out;
    cudaFuncSetAttribute(self_attn_fused_kernel,
                         cudaFuncAttributeMaxDynamicSharedMemorySize, SMEM_BYTES);
    self_attn_fused_kernel<<<NTILES/TPB, NTHREADS, SMEM_BYTES>>>(frames, out);
}

// round 17
// speedup vs baseline: 1.8333x; 1.8333x over previous
#include <cuda_runtime.h>
#include <cstdint>

// self_attention_76416058130984 — GB300 sm_103a
// frames: [4, B=8, C=64, H=160, W=160] fp32 -> out: [8, 256, 160, 160] fp32
//
// Per pixel: E_ij(c) = exp(x_i[c]*x_j[c]) (symmetric, 10 unique per channel),
// denom_i = sum_{j,c} E_ij(c),  out_i[c] = (sum_j E_ij(c)*x_j[c]) / denom_i.
// No max-subtraction needed (logits bounded ~40, fp32 safe; softmax shift-invariant).
//
// R17 = R11's inner loop EXACTLY (WTILE=32 / 128B GMEM rows, cp.async
// double-buffer, lane=pixel mapping, pd cross-warp reduce, y in smem,
// plain float4 stores) made PERSISTENT: 444 blocks (148 SM x 3 resident),
// grid-stride over 6400 tiles. Prologues 1600->444, no wave tail, pipeline
// never drains. Laws honored: >=128B per GMEM row (R16), no .cs (R12/R13),
// y in smem / regs<=~65 (R13), no unroll pressure (R12).

#define B_       8
#define C_       64
#define H_       160
#define W_       160
#define HW_      (H_*W_)            // 25600
#define WTILE    32
#define NTHREADS 256
#define NBLOCKS  444                // 148 SMs x 3 resident = one persistent wave
#define NTILES   (B_*H_*(W_/WTILE)) // 6400
#define TILE_F   (4*C_*WTILE)       // 8192 floats = 32KB
#define PD_OFF   (2*TILE_F)         // pd[8 warps][4 i][32 px] = 1024 floats
#define INVD_OFF (PD_OFF + 8*4*32)  // invd[4 i][32 px] = 128 floats
#define SMEM_F   (INVD_OFF + 4*32)  // 17664 floats
#define SMEM_BYTES (SMEM_F*4)       // 70656 B -> 3 blocks/SM

__device__ __forceinline__ float ex2a(float x) {
    float y; asm("ex2.approx.f32 %0, %1;" : "=f"(y) : "f"(x)); return y;
}
__device__ __forceinline__ float rcpa(float x) {
    float y; asm("rcp.approx.f32 %0, %1;" : "=f"(y) : "f"(x)); return y;
}
__device__ __forceinline__ void cpasync16(uint32_t dst_s, const void* src_g) {
    asm volatile("cp.async.cg.shared.global [%0], [%1], 16;"
                 :: "r"(dst_s), "l"(src_g));
}

// 10 unique exps -> row sums r[i] and gated sums y[i]
__device__ __forceinline__ void attn4(const float a[4], float y[4], float r[4]) {
    const float L2E = 1.44269504f;   // log2(e)
    float b0 = a[0]*L2E, b1 = a[1]*L2E, b2 = a[2]*L2E, b3 = a[3]*L2E;
    float e00 = ex2a(a[0]*b0), e01 = ex2a(a[0]*b1), e02 = ex2a(a[0]*b2), e03 = ex2a(a[0]*b3);
    float e11 = ex2a(a[1]*b1), e12 = ex2a(a[1]*b2), e13 = ex2a(a[1]*b3);
    float e22 = ex2a(a[2]*b2), e23 = ex2a(a[2]*b3);
    float e33 = ex2a(a[3]*b3);
    r[0] = (e00+e01)+(e02+e03);
    r[1] = (e01+e11)+(e12+e13);
    r[2] = (e02+e12)+(e22+e23);
    r[3] = (e03+e13)+(e23+e33);
    y[0] = fmaf(e00,a[0], fmaf(e01,a[1], fmaf(e02,a[2], e03*a[3])));
    y[1] = fmaf(e01,a[0], fmaf(e11,a[1], fmaf(e12,a[2], e13*a[3])));
    y[2] = fmaf(e02,a[0], fmaf(e12,a[1], fmaf(e22,a[2], e23*a[3])));
    y[3] = fmaf(e03,a[0], fmaf(e13,a[1], fmaf(e23,a[2], e33*a[3])));
}

// async-copy one 32-pixel tile (256 rows x 32 floats) into smem buffer
__device__ __forceinline__ void ca_tile(uint32_t dst_s, int tid, int t,
                                        const float* __restrict__ frames) {
    const int tl = tid % (W_/WTILE);
    const int h  = (tid / (W_/WTILE)) % H_;
    const int b  = tid / ((W_/WTILE)*H_);
    const int sp = h*W_ + tl*WTILE;
    #pragma unroll
    for (int m = 0; m < 8; ++m) {
        const int f   = m*NTHREADS + t;   // 0..2047 quad index
        const int row = f >> 3;           // j*64 + c
        const int q   = f & 7;
        const int j   = row >> 6;
        const int c   = row & 63;
        cpasync16(dst_s + (uint32_t)(row*WTILE + q*4)*4u,
                  frames + ((j*B_ + b)*C_ + c)*HW_ + sp + q*4);
    }
}

__global__ void __launch_bounds__(NTHREADS)
self_attn_fused_kernel(const float* __restrict__ frames, float* __restrict__ out)
{
    extern __shared__ float s[];
    const uint32_t s_u32 = (uint32_t)__cvta_generic_to_shared(s);
    const int t    = threadIdx.x;
    const int warp = t >> 5, lane = t & 31;

    // prologue: prefetch this block's first tile
    int tid = blockIdx.x;
    ca_tile(s_u32, tid, t, frames);
    asm volatile("cp.async.commit_group;");

    int par = 0;
    for (; tid < NTILES; tid += NBLOCKS, par ^= 1) {
        float* buf = s + par*TILE_F;

        // prefetch the next tile in this block's stride into the other
        // buffer, then wait for the current tile
        const int nxt = tid + NBLOCKS;
        if (nxt < NTILES) {
            ca_tile(s_u32 + (uint32_t)((par^1)*TILE_F)*4u, nxt, t, frames);
            asm volatile("cp.async.commit_group;");
            asm volatile("cp.async.wait_group 1;");
        } else {
            asm volatile("cp.async.wait_group 0;");
        }
        __syncthreads();

        // ---- Phase 2a: lane = pixel, warp owns channels [8w, 8w+8)
        // accumulate local partial denominators; write unnormalized y in place
        // (warp w touches only rows {*64 + c : c in its slice} -> disjoint)
        float d[4] = {0.f, 0.f, 0.f, 0.f};
        #pragma unroll
        for (int cc = 0; cc < 8; ++cc) {
            const int c = warp*8 + cc;
            float a[4];
            #pragma unroll
            for (int j = 0; j < 4; ++j)
                a[j] = buf[(j*C_ + c)*WTILE + lane];
            float y[4], r[4];
            attn4(a, y, r);
            #pragma unroll
            for (int i = 0; i < 4; ++i) {
                d[i] += r[i];
                buf[(i*C_ + c)*WTILE + lane] = y[i];
            }
        }
        #pragma unroll
        for (int i = 0; i < 4; ++i)
            s[PD_OFF + (warp*4 + i)*32 + lane] = d[i];
        __syncthreads();

        // ---- Phase 2b: reduce partial denoms across 8 warps, one rcp each
        if (t < 128) {
            const int i = t >> 5, p = t & 31;
            float sum = 0.f;
            #pragma unroll
            for (int w = 0; w < 8; ++w)
                sum += s[PD_OFF + (w*4 + i)*32 + p];
            s[INVD_OFF + i*32 + p] = rcpa(sum);
        }
        __syncthreads();

        // ---- Phase 3: normalize + coalesced store
        {
            const int tl = tid % (W_/WTILE);
            const int h  = (tid / (W_/WTILE)) % H_;
            const int b  = tid / ((W_/WTILE)*H_);
            const int sp = h*W_ + tl*WTILE;
            const int row0 = t >> 3;          // 0..31
            const int q4   = (t & 7)*4;       // 0..28
            #pragma unroll
            for (int it = 0; it < 8; ++it) {
                const int row = row0 + it*32; // i*64 + c
                const int i   = row >> 6;
                const float4 iv = *reinterpret_cast<const float4*>(
                    s + INVD_OFF + i*32 + q4);
                const float* yp = buf + row*WTILE + q4;
                float4 v = make_float4(yp[0]*iv.x, yp[1]*iv.y,
                                       yp[2]*iv.z, yp[3]*iv.w);
                *reinterpret_cast<float4*>(
                    out + (b*4*C_ + row)*HW_ + sp + q4) = v;
            }
        }
        __syncthreads();   // protect buf/pd/invd reuse vs next iteration's cp.async
    }
}

extern "C" void kernel_launch(void* const* d_in, const int* in_sizes, int n_in,
                              void* d_out, int out_size)
{
    const float* frames = (const float*)d_in[0];
    float* out = (float*)d_out;
    cudaFuncSetAttribute(self_attn_fused_kernel,
                         cudaFuncAttributeMaxDynamicSharedMemorySize, SMEM_BYTES);
    self_attn_fused_kernel<<<NBLOCKS, NTHREADS, SMEM_BYTES>>>(frames, out);
}